// round 13
// baseline (speedup 1.0000x reference)
#include <cuda_runtime.h>
#include <math.h>
#include <stdint.h>

#define BATCH   32
#define SEQ     577
#define SPAD    580                  /* V seq stride: 580*4B = 16B-aligned */
#define HEADS   12
#define DH      64
#define DMODEL  768
#define MROWS   (BATCH*SEQ)          /* 18464 */
#define QKSCALE 0.125f
#define HEADSZ  14180352u            /* 32*12*577*64 */
#define VSZ     (32u*12u*64u*SPAD)   /* 14254080 */

// Scratch (tf32 bit patterns downstream of the prepass).
__device__ unsigned g_qkv[2u * HEADSZ];          // Q,K: [B,H,S,DH] (Q pre-scaled)
__device__ unsigned g_v  [VSZ];                  // V: [B,H,D,SPAD] d-major (zero-init tail)
__device__ unsigned g_att[HEADSZ];               // [B*S, DMODEL]
__device__ unsigned g_xt [HEADSZ];               // x
__device__ unsigned g_wqt[3 * DMODEL * DMODEL];  // w_qkv^T [2304][768]
__device__ unsigned g_wft[DMODEL * DMODEL];      // w_fc^T  [768][768]

__device__ __forceinline__ unsigned f2tf(float f) {
    unsigned u; asm("cvt.rna.tf32.f32 %0, %1;" : "=r"(u) : "f"(f)); return u;
}

__device__ __forceinline__ void mma8(float* c, unsigned a0, unsigned a1, unsigned a2,
                                     unsigned a3, unsigned b0, unsigned b1) {
    asm volatile(
        "mma.sync.aligned.m16n8k8.row.col.f32.tf32.tf32.f32 "
        "{%0,%1,%2,%3}, {%4,%5,%6,%7}, {%8,%9}, {%0,%1,%2,%3};\n"
        : "+f"(c[0]), "+f"(c[1]), "+f"(c[2]), "+f"(c[3])
        : "r"(a0), "r"(a1), "r"(a2), "r"(a3), "r"(b0), "r"(b1));
}

// One LDSM: 4 tf32 8x4 fragment tiles (as 8x8 b16 tiles)
#define LDSM4(r0, r1, r2, r3, addr)                                          \
    asm volatile("ldmatrix.sync.aligned.m8n8.x4.shared.b16 {%0,%1,%2,%3}, [%4];" \
        : "=r"(r0), "=r"(r1), "=r"(r2), "=r"(r3) : "r"(addr))

__device__ __forceinline__ void cp16(void* smem_dst, const void* gsrc, bool pred) {
    unsigned d = (unsigned)__cvta_generic_to_shared(smem_dst);
    int sz = pred ? 16 : 0;
    asm volatile("cp.async.cg.shared.global [%0], [%1], 16, %2;\n"
                 :: "r"(d), "l"(gsrc), "r"(sz));
}
__device__ __forceinline__ void cp_commit() { asm volatile("cp.async.commit_group;\n"); }
template<int N> __device__ __forceinline__ void cp_wait() {
    asm volatile("cp.async.wait_group %0;\n" :: "n"(N));
}

// ---------------------------------------------------------------------------
// Prepass: x -> tf32; weights -> transposed tf32
// ---------------------------------------------------------------------------
__global__ __launch_bounds__(256)
void cvt_kernel(const float* __restrict__ src, int n4)
{
    int i = blockIdx.x * blockDim.x + threadIdx.x;
    if (i < n4) {
        float4 v = ((const float4*)src)[i];
        uint4 u;
        u.x = f2tf(v.x); u.y = f2tf(v.y); u.z = f2tf(v.z); u.w = f2tf(v.w);
        ((uint4*)g_xt)[i] = u;
    }
}

// src [R][C] fp32 -> dst [C][R] tf32.  sel: 1=g_wqt, 2=g_wft
__global__ __launch_bounds__(256)
void trcvt_kernel(const float* __restrict__ src, int sel, int R, int C)
{
    __shared__ unsigned t[32][33];
    unsigned* dst = (sel == 1) ? g_wqt : g_wft;
    int c0 = blockIdx.x * 32, r0 = blockIdx.y * 32;
    int tx = threadIdx.x & 31, ty = threadIdx.x >> 5;
    #pragma unroll
    for (int i = 0; i < 32; i += 8)
        t[ty + i][tx] = f2tf(src[(size_t)(r0 + ty + i) * C + c0 + tx]);
    __syncthreads();
    #pragma unroll
    for (int i = 0; i < 32; i += 8)
        dst[(size_t)(c0 + ty + i) * R + r0 + tx] = t[tx][ty + i];
}

// ---------------------------------------------------------------------------
// TF32 GEMM, LDSM fragments, 3-stage cp.async pipeline with ONE barrier/slab:
//   wait -> sync -> stage(t+2) -> compute(t)
// (stage(t+2) writes buf (t-1)%3; sync(t) guarantees compute(t-1) is done.)
// Block 128x128x32, 256 thr, 8 warps (2Mx4N), warp tile 64x32.
// MODE 0 -> Q/K scatter (scaled tf32) + V d-major; MODE 1 -> out fp32.
// ---------------------------------------------------------------------------
#define TST 36
#define TBUF (128 * TST)    /* 4608 words */
#define NST 3
#define GEMM_SMEM (NST * 2 * TBUF * 4)   /* 110592 B */

template<int MODE>
__global__ __launch_bounds__(256, 2)
void gemm_kernel(const float* __restrict__ bias, float* __restrict__ out, int N)
{
    extern __shared__ unsigned sm[];
    const unsigned smU = (unsigned)__cvta_generic_to_shared(sm);
    unsigned* Asm = sm;                    // NST buffers
    unsigned* Bsm = sm + NST * TBUF;       // NST buffers
    const unsigned* A  = (MODE == 0) ? g_xt : g_att;
    const unsigned* Wt = (MODE == 0) ? g_wqt : g_wft;
    const int K = DMODEL;

    const int tid  = threadIdx.x;
    const int warp = tid >> 5, lane = tid & 31;
    const int g = lane >> 2, l4 = lane & 3;
    const int wm = warp >> 2, wn = warp & 3;
    const int m0 = blockIdx.x * 128, n0 = blockIdx.y * 128;

    const int laneArow = ((lane >> 3) & 1) * 8 + (lane & 7);
    const int laneAcol = (lane >> 4) * 4;
    const int laneBrow = (lane >> 4) * 8 + (lane & 7);
    const int laneBcol = ((lane >> 3) & 1) * 4;

    float c[4][4][4];
    #pragma unroll
    for (int i = 0; i < 4; i++)
        #pragma unroll
        for (int j = 0; j < 4; j++)
            #pragma unroll
            for (int r = 0; r < 4; r++) c[i][j][r] = 0.f;

    auto stage = [&](int slab) {
        const int kc = slab * 32;
        const int buf = slab % NST;
        unsigned* Ab = Asm + buf * TBUF;
        unsigned* Bb = Bsm + buf * TBUF;
        #pragma unroll
        for (int it = 0; it < 4; it++) {
            int idx = tid + it * 256;          // 1024: 128 rows x 8 chunks
            int row = idx >> 3, q = idx & 7;
            int gm = m0 + row;
            bool p = gm < MROWS;
            cp16(Ab + row * TST + q * 4, A + (size_t)(p ? gm : 0) * K + kc + q * 4, p);
        }
        #pragma unroll
        for (int it = 0; it < 4; it++) {
            int idx = tid + it * 256;
            int row = idx >> 3, q = idx & 7;
            cp16(Bb + row * TST + q * 4, Wt + (size_t)(n0 + row) * K + kc + q * 4, true);
        }
        cp_commit();
    };

    stage(0);
    stage(1);
    #pragma unroll 1
    for (int t = 0; t < 24; t++) {             // K/32
        if (t < 22) cp_wait<1>(); else cp_wait<0>();
        __syncthreads();
        if (t + 2 < 24) stage(t + 2);

        const unsigned AbU = smU + (t % NST) * TBUF * 4;
        const unsigned BbU = smU + (NST + t % NST) * TBUF * 4;
        #pragma unroll
        for (int ks = 0; ks < 4; ks++) {
            const int kk = ks * 8;
            unsigned a[4][4];
            #pragma unroll
            for (int mt = 0; mt < 4; mt++)
                LDSM4(a[mt][0], a[mt][1], a[mt][2], a[mt][3],
                      AbU + 4u * ((wm * 64 + mt * 16 + laneArow) * TST + kk + laneAcol));
            #pragma unroll
            for (int ntp = 0; ntp < 4; ntp += 2) {
                unsigned b0, b1, b2, b3;
                LDSM4(b0, b1, b2, b3,
                      BbU + 4u * ((wn * 32 + ntp * 8 + laneBrow) * TST + kk + laneBcol));
                #pragma unroll
                for (int mt = 0; mt < 4; mt++) {
                    mma8(c[mt][ntp    ], a[mt][0], a[mt][1], a[mt][2], a[mt][3], b0, b1);
                    mma8(c[mt][ntp + 1], a[mt][0], a[mt][1], a[mt][2], a[mt][3], b2, b3);
                }
            }
        }
    }

    // Epilogue
    #pragma unroll
    for (int mt = 0; mt < 4; mt++)
        #pragma unroll
        for (int nt = 0; nt < 4; nt++)
            #pragma unroll
            for (int jr = 0; jr < 2; jr++) {
                int m = m0 + wm * 64 + mt * 16 + g + jr * 8;
                int n = n0 + wn * 32 + nt * 8 + 2 * l4;
                if (m < MROWS) {
                    float v0 = c[mt][nt][2 * jr    ] + bias[n    ];
                    float v1 = c[mt][nt][2 * jr + 1] + bias[n + 1];
                    if (MODE == 0) {
                        int part = n / DMODEL, rem = n % DMODEL;
                        int h = rem >> 6, d = rem & 63;
                        int b = m / SEQ, s = m % SEQ;
                        if (part == 2) {
                            size_t vb = ((size_t)(b * HEADS + h) * DH + d) * SPAD + s;
                            g_v[vb       ] = f2tf(v0);
                            g_v[vb + SPAD] = f2tf(v1);
                        } else {
                            if (part == 0) { v0 *= QKSCALE; v1 *= QKSCALE; }
                            uint2 u; u.x = f2tf(v0); u.y = f2tf(v1);
                            *(uint2*)&g_qkv[(size_t)part * HEADSZ +
                                (((size_t)(b * HEADS + h) * SEQ + s) * DH + d)] = u;
                        }
                    } else {
                        float2 f; f.x = v0; f.y = v1;
                        *(float2*)&out[(size_t)m * DMODEL + n] = f;
                    }
                }
            }
}

// ---------------------------------------------------------------------------
// Flash attention, LDSM fragments, single barrier per key tile:
//   wait -> sync -> stage(kt+1) -> compute(kt)
// K smem [key][d]; V smem [d][key]; P spilled [qrow][key] (warp-private).
// ---------------------------------------------------------------------------
#define KST 68
#define KBUF (64 * KST)
#define PS_OFF (4 * KBUF)
#define ATT_SMEM ((PS_OFF + 128 * KST) * 4)   /* 104448 B */

__global__ __launch_bounds__(256, 2)
void attn_kernel()
{
    extern __shared__ unsigned sm[];
    const unsigned smU = (unsigned)__cvta_generic_to_shared(sm);
    unsigned* KsA = sm;                    // 2 buffers [64][68]
    unsigned* VsA = sm + 2 * KBUF;         // 2 buffers [64][68] (d-major)
    unsigned* Ps  = sm + PS_OFF;           // [128][68]
    const unsigned PsU = smU + PS_OFF * 4;

    const int tid  = threadIdx.x;
    const int warp = tid >> 5, lane = tid & 31;
    const int g = lane >> 2, l4 = lane & 3;
    const int bh = blockIdx.y;
    const int b = bh / HEADS, h = bh % HEADS;
    const int q0 = blockIdx.x * 128;
    const int qr = q0 + warp * 16;

    const int laneArow = ((lane >> 3) & 1) * 8 + (lane & 7);
    const int laneAcol = (lane >> 4) * 4;
    const int laneBrow = (lane >> 4) * 8 + (lane & 7);
    const int laneBcol = ((lane >> 3) & 1) * 4;

    const size_t base = (size_t)(b * HEADS + h) * SEQ * DH;
    const unsigned* Qg = g_qkv + base;
    const unsigned* Kg = g_qkv + HEADSZ + base;
    const unsigned* Vg = g_v + (size_t)(b * HEADS + h) * DH * SPAD;

    // Preload Q fragments (tf32, pre-scaled)
    unsigned qa[8][4];
    {
        const int r0 = qr + g, r1 = qr + g + 8;
        #pragma unroll
        for (int ks = 0; ks < 8; ks++) {
            int c0 = ks * 8 + l4;
            qa[ks][0] = (r0 < SEQ) ? Qg[r0 * DH + c0    ] : 0u;
            qa[ks][1] = (r1 < SEQ) ? Qg[r1 * DH + c0    ] : 0u;
            qa[ks][2] = (r0 < SEQ) ? Qg[r0 * DH + c0 + 4] : 0u;
            qa[ks][3] = (r1 < SEQ) ? Qg[r1 * DH + c0 + 4] : 0u;
        }
    }

    float o[8][4];
    #pragma unroll
    for (int nt = 0; nt < 8; nt++)
        #pragma unroll
        for (int r = 0; r < 4; r++) o[nt][r] = 0.f;
    float lrow[2] = {0.f, 0.f};

    auto stageKV = [&](int kt) {
        int k0 = kt * 64;
        int kv = SEQ - k0; if (kv > 64) kv = 64;
        int buf = kt & 1;
        unsigned* Kb = KsA + buf * KBUF;
        unsigned* Vb = VsA + buf * KBUF;
        #pragma unroll
        for (int it = 0; it < 4; it++) {
            int idx = tid + it * 256;
            int row = idx >> 4, q = idx & 15;
            bool pk = row < kv;
            int rk = pk ? (k0 + row) : 0;
            cp16(Kb + row * KST + q * 4, Kg + (size_t)rk * DH + q * 4, pk);
            bool pv = (q * 4) < kv;
            cp16(Vb + row * KST + q * 4, Vg + (size_t)row * SPAD + k0 + q * 4, pv);
        }
        cp_commit();
    };

    const int NTILES = (SEQ + 63) / 64;   // 10
    stageKV(0);
    #pragma unroll 1
    for (int kt = 0; kt < NTILES; kt++) {
        cp_wait<0>();
        __syncthreads();
        if (kt + 1 < NTILES) stageKV(kt + 1);

        const int k0 = kt * 64;
        int kv = SEQ - k0; if (kv > 64) kv = 64;
        const unsigned KbU = smU + (kt & 1) * KBUF * 4;
        const unsigned VbU = smU + (2 + (kt & 1)) * KBUF * 4;

        // S = Q K^T
        float s[8][4];
        #pragma unroll
        for (int nt = 0; nt < 8; nt++)
            #pragma unroll
            for (int r = 0; r < 4; r++) s[nt][r] = 0.f;

        #pragma unroll
        for (int ks = 0; ks < 8; ks++) {
            const int kk = ks * 8;
            #pragma unroll
            for (int ntp = 0; ntp < 8; ntp += 2) {
                unsigned b0, b1, b2, b3;
                LDSM4(b0, b1, b2, b3,
                      KbU + 4u * ((ntp * 8 + laneBrow) * KST + kk + laneBcol));
                mma8(s[ntp    ], qa[ks][0], qa[ks][1], qa[ks][2], qa[ks][3], b0, b1);
                mma8(s[ntp + 1], qa[ks][0], qa[ks][1], qa[ks][2], qa[ks][3], b2, b3);
            }
        }

        // exp + masked sum (no max-shift needed: scores bounded)
        #pragma unroll
        for (int r = 0; r < 2; r++) {
            float sum = 0.f;
            #pragma unroll
            for (int nt = 0; nt < 8; nt++) {
                int col = nt * 8 + 2 * l4;
                float p0 = (col     < kv) ? __expf(s[nt][2 * r    ]) : 0.f;
                float p1 = (col + 1 < kv) ? __expf(s[nt][2 * r + 1]) : 0.f;
                s[nt][2 * r] = p0; s[nt][2 * r + 1] = p1;
                sum += p0 + p1;
            }
            sum += __shfl_xor_sync(0xffffffffu, sum, 1);
            sum += __shfl_xor_sync(0xffffffffu, sum, 2);
            lrow[r] += sum;
        }

        // Spill P (tf32) to warp-private rows
        {
            const int r0 = warp * 16 + g, r1 = r0 + 8;
            #pragma unroll
            for (int nt = 0; nt < 8; nt++) {
                Ps[r0 * KST + nt * 8 + 2 * l4    ] = f2tf(s[nt][0]);
                Ps[r0 * KST + nt * 8 + 2 * l4 + 1] = f2tf(s[nt][1]);
                Ps[r1 * KST + nt * 8 + 2 * l4    ] = f2tf(s[nt][2]);
                Ps[r1 * KST + nt * 8 + 2 * l4 + 1] = f2tf(s[nt][3]);
            }
        }
        __syncwarp();

        // O += P V
        #pragma unroll
        for (int ks = 0; ks < 8; ks++) {
            const int kk = ks * 8;
            unsigned pa0, pa1, pa2, pa3;
            LDSM4(pa0, pa1, pa2, pa3,
                  PsU + 4u * ((warp * 16 + laneArow) * KST + kk + laneAcol));
            #pragma unroll
            for (int ntp = 0; ntp < 8; ntp += 2) {
                unsigned b0, b1, b2, b3;
                LDSM4(b0, b1, b2, b3,
                      VbU + 4u * ((ntp * 8 + laneBrow) * KST + kk + laneBcol));
                mma8(o[ntp    ], pa0, pa1, pa2, pa3, b0, b1);
                mma8(o[ntp + 1], pa0, pa1, pa2, pa3, b2, b3);
            }
        }
    }

    // Normalize, write g_att (tf32)
    #pragma unroll
    for (int r = 0; r < 2; r++) {
        int row = qr + g + r * 8;
        if (row < SEQ) {
            float inv = 1.f / lrow[r];
            size_t rb = ((size_t)b * SEQ + row) * DMODEL + h * DH;
            #pragma unroll
            for (int nt = 0; nt < 8; nt++) {
                uint2 u;
                u.x = f2tf(o[nt][2 * r    ] * inv);
                u.y = f2tf(o[nt][2 * r + 1] * inv);
                *(uint2*)&g_att[rb + nt * 8 + 2 * l4] = u;
            }
        }
    }
}

// ---------------------------------------------------------------------------
extern "C" void kernel_launch(void* const* d_in, const int* in_sizes, int n_in,
                              void* d_out, int out_size)
{
    const float* x     = (const float*)d_in[0];
    const float* w_qkv = (const float*)d_in[1];
    const float* b_qkv = (const float*)d_in[2];
    const float* w_fc  = (const float*)d_in[3];
    const float* b_fc  = (const float*)d_in[4];
    float* out = (float*)d_out;

    cudaFuncSetAttribute(gemm_kernel<0>, cudaFuncAttributeMaxDynamicSharedMemorySize, GEMM_SMEM);
    cudaFuncSetAttribute(gemm_kernel<1>, cudaFuncAttributeMaxDynamicSharedMemorySize, GEMM_SMEM);
    cudaFuncSetAttribute(attn_kernel,    cudaFuncAttributeMaxDynamicSharedMemorySize, ATT_SMEM);

    // Prepass: x -> tf32; weights -> transposed tf32
    cvt_kernel<<<(HEADSZ / 4 + 255) / 256, 256>>>(x, HEADSZ / 4);
    trcvt_kernel<<<dim3(3 * DMODEL / 32, DMODEL / 32), 256>>>(w_qkv, 1, DMODEL, 3 * DMODEL);
    trcvt_kernel<<<dim3(DMODEL / 32, DMODEL / 32), 256>>>(w_fc, 2, DMODEL, DMODEL);

    const int mtiles = (MROWS + 127) / 128;   // 145
    gemm_kernel<0><<<dim3(mtiles, 18), 256, GEMM_SMEM>>>(b_qkv, nullptr, 3 * DMODEL);
    attn_kernel<<<dim3((SEQ + 127) / 128, BATCH * HEADS), 256, ATT_SMEM>>>();
    gemm_kernel<1><<<dim3(mtiles, 6), 256, GEMM_SMEM>>>(b_fc, out, DMODEL);
}

// round 14
// speedup vs baseline: 1.0090x; 1.0090x over previous
#include <cuda_runtime.h>
#include <math.h>
#include <stdint.h>

#define BATCH   32
#define SEQ     577
#define SPAD    580                  /* V seq stride: 580*4B = 16B-aligned */
#define HEADS   12
#define DH      64
#define DMODEL  768
#define MROWS   (BATCH*SEQ)          /* 18464 */
#define QKSCALE 0.125f
#define HEADSZ  14180352u            /* 32*12*577*64 */
#define VSZ     (32u*12u*64u*SPAD)   /* 14254080 */

// Scratch (tf32 bit patterns downstream of the prepass).
__device__ unsigned g_qkv[2u * HEADSZ];          // Q,K: [B,H,S,DH] (Q pre-scaled)
__device__ unsigned g_v  [VSZ];                  // V: [B,H,D,SPAD] d-major (zero-init tail)
__device__ unsigned g_att[HEADSZ];               // [B*S, DMODEL]
__device__ unsigned g_xt [HEADSZ];               // x
__device__ unsigned g_wqt[3 * DMODEL * DMODEL];  // w_qkv^T [2304][768]
__device__ unsigned g_wft[DMODEL * DMODEL];      // w_fc^T  [768][768]

__device__ __forceinline__ unsigned f2tf(float f) {
    unsigned u; asm("cvt.rna.tf32.f32 %0, %1;" : "=r"(u) : "f"(f)); return u;
}

// NOTE: non-volatile on purpose — pure register computation; lets the compiler
// sink mmas below the next ks-step's LDSMs (software pipelining across steps).
__device__ __forceinline__ void mma8(float* c, unsigned a0, unsigned a1, unsigned a2,
                                     unsigned a3, unsigned b0, unsigned b1) {
    asm("mma.sync.aligned.m16n8k8.row.col.f32.tf32.tf32.f32 "
        "{%0,%1,%2,%3}, {%4,%5,%6,%7}, {%8,%9}, {%0,%1,%2,%3};\n"
        : "+f"(c[0]), "+f"(c[1]), "+f"(c[2]), "+f"(c[3])
        : "r"(a0), "r"(a1), "r"(a2), "r"(a3), "r"(b0), "r"(b1));
}

// One LDSM: 4 tf32 8x4 fragment tiles (as 8x8 b16 tiles). Stays volatile
// (reads smem; must not move across barriers).
#define LDSM4(r0, r1, r2, r3, addr)                                          \
    asm volatile("ldmatrix.sync.aligned.m8n8.x4.shared.b16 {%0,%1,%2,%3}, [%4];" \
        : "=r"(r0), "=r"(r1), "=r"(r2), "=r"(r3) : "r"(addr))

__device__ __forceinline__ void cp16(void* smem_dst, const void* gsrc, bool pred) {
    unsigned d = (unsigned)__cvta_generic_to_shared(smem_dst);
    int sz = pred ? 16 : 0;
    asm volatile("cp.async.cg.shared.global [%0], [%1], 16, %2;\n"
                 :: "r"(d), "l"(gsrc), "r"(sz));
}
__device__ __forceinline__ void cp_commit() { asm volatile("cp.async.commit_group;\n"); }
template<int N> __device__ __forceinline__ void cp_wait() {
    asm volatile("cp.async.wait_group %0;\n" :: "n"(N));
}

// ---------------------------------------------------------------------------
// Prepass: x -> tf32; weights -> transposed tf32
// ---------------------------------------------------------------------------
__global__ __launch_bounds__(256)
void cvt_kernel(const float* __restrict__ src, int n4)
{
    int i = blockIdx.x * blockDim.x + threadIdx.x;
    if (i < n4) {
        float4 v = ((const float4*)src)[i];
        uint4 u;
        u.x = f2tf(v.x); u.y = f2tf(v.y); u.z = f2tf(v.z); u.w = f2tf(v.w);
        ((uint4*)g_xt)[i] = u;
    }
}

// src [R][C] fp32 -> dst [C][R] tf32.  sel: 1=g_wqt, 2=g_wft
__global__ __launch_bounds__(256)
void trcvt_kernel(const float* __restrict__ src, int sel, int R, int C)
{
    __shared__ unsigned t[32][33];
    unsigned* dst = (sel == 1) ? g_wqt : g_wft;
    int c0 = blockIdx.x * 32, r0 = blockIdx.y * 32;
    int tx = threadIdx.x & 31, ty = threadIdx.x >> 5;
    #pragma unroll
    for (int i = 0; i < 32; i += 8)
        t[ty + i][tx] = f2tf(src[(size_t)(r0 + ty + i) * C + c0 + tx]);
    __syncthreads();
    #pragma unroll
    for (int i = 0; i < 32; i += 8)
        dst[(size_t)(c0 + ty + i) * R + r0 + tx] = t[tx][ty + i];
}

// ---------------------------------------------------------------------------
// TF32 GEMM with LDSM fragments.  C[M,N] = A[M,768] * W^T + bias
// Block 128x128x32, 256 thr, 8 warps (2Mx4N), warp tile 64x32.
// 2-stage cp.async double buffer (best measured structure, R10).
// MODE 0 -> Q/K scatter (scaled tf32) + V d-major; MODE 1 -> out fp32.
// ---------------------------------------------------------------------------
#define TST 36
#define TBUF (128 * TST)    /* 4608 words */
#define GEMM_SMEM (4 * TBUF * 4)   /* 73728 B */

template<int MODE>
__global__ __launch_bounds__(256, 2)
void gemm_kernel(const float* __restrict__ bias, float* __restrict__ out, int N)
{
    extern __shared__ unsigned sm[];
    const unsigned smU = (unsigned)__cvta_generic_to_shared(sm);
    unsigned* Asm = sm;                    // 2 buffers
    unsigned* Bsm = sm + 2 * TBUF;         // 2 buffers
    const unsigned* A  = (MODE == 0) ? g_xt : g_att;
    const unsigned* Wt = (MODE == 0) ? g_wqt : g_wft;
    const int K = DMODEL;

    const int tid  = threadIdx.x;
    const int warp = tid >> 5, lane = tid & 31;
    const int g = lane >> 2, l4 = lane & 3;
    const int wm = warp >> 2, wn = warp & 3;
    const int m0 = blockIdx.x * 128, n0 = blockIdx.y * 128;

    const int laneArow = ((lane >> 3) & 1) * 8 + (lane & 7);
    const int laneAcol = (lane >> 4) * 4;
    const int laneBrow = (lane >> 4) * 8 + (lane & 7);
    const int laneBcol = ((lane >> 3) & 1) * 4;

    float c[4][4][4];
    #pragma unroll
    for (int i = 0; i < 4; i++)
        #pragma unroll
        for (int j = 0; j < 4; j++)
            #pragma unroll
            for (int r = 0; r < 4; r++) c[i][j][r] = 0.f;

    auto stage = [&](int slab, int buf) {
        const int kc = slab * 32;
        unsigned* Ab = Asm + buf * TBUF;
        unsigned* Bb = Bsm + buf * TBUF;
        #pragma unroll
        for (int it = 0; it < 4; it++) {
            int idx = tid + it * 256;          // 1024: 128 rows x 8 chunks
            int row = idx >> 3, q = idx & 7;
            int gm = m0 + row;
            bool p = gm < MROWS;
            cp16(Ab + row * TST + q * 4, A + (size_t)(p ? gm : 0) * K + kc + q * 4, p);
        }
        #pragma unroll
        for (int it = 0; it < 4; it++) {
            int idx = tid + it * 256;
            int row = idx >> 3, q = idx & 7;
            cp16(Bb + row * TST + q * 4, Wt + (size_t)(n0 + row) * K + kc + q * 4, true);
        }
        cp_commit();
    };

    stage(0, 0);
    #pragma unroll 1
    for (int t = 0; t < 24; t++) {             // K/32
        if (t < 23) { stage(t + 1, (t + 1) & 1); cp_wait<1>(); }
        else        { cp_wait<0>(); }
        __syncthreads();

        const unsigned AbU = smU + (t & 1) * TBUF * 4;
        const unsigned BbU = smU + (2 + (t & 1)) * TBUF * 4;
        #pragma unroll
        for (int ks = 0; ks < 4; ks++) {
            const int kk = ks * 8;
            unsigned a[4][4];
            #pragma unroll
            for (int mt = 0; mt < 4; mt++)
                LDSM4(a[mt][0], a[mt][1], a[mt][2], a[mt][3],
                      AbU + 4u * ((wm * 64 + mt * 16 + laneArow) * TST + kk + laneAcol));
            #pragma unroll
            for (int ntp = 0; ntp < 4; ntp += 2) {
                unsigned b0, b1, b2, b3;
                LDSM4(b0, b1, b2, b3,
                      BbU + 4u * ((wn * 32 + ntp * 8 + laneBrow) * TST + kk + laneBcol));
                #pragma unroll
                for (int mt = 0; mt < 4; mt++) {
                    mma8(c[mt][ntp    ], a[mt][0], a[mt][1], a[mt][2], a[mt][3], b0, b1);
                    mma8(c[mt][ntp + 1], a[mt][0], a[mt][1], a[mt][2], a[mt][3], b2, b3);
                }
            }
        }
        __syncthreads();
    }

    // Epilogue
    #pragma unroll
    for (int mt = 0; mt < 4; mt++)
        #pragma unroll
        for (int nt = 0; nt < 4; nt++)
            #pragma unroll
            for (int jr = 0; jr < 2; jr++) {
                int m = m0 + wm * 64 + mt * 16 + g + jr * 8;
                int n = n0 + wn * 32 + nt * 8 + 2 * l4;
                if (m < MROWS) {
                    float v0 = c[mt][nt][2 * jr    ] + bias[n    ];
                    float v1 = c[mt][nt][2 * jr + 1] + bias[n + 1];
                    if (MODE == 0) {
                        int part = n / DMODEL, rem = n % DMODEL;
                        int h = rem >> 6, d = rem & 63;
                        int b = m / SEQ, s = m % SEQ;
                        if (part == 2) {
                            size_t vb = ((size_t)(b * HEADS + h) * DH + d) * SPAD + s;
                            g_v[vb       ] = f2tf(v0);
                            g_v[vb + SPAD] = f2tf(v1);
                        } else {
                            if (part == 0) { v0 *= QKSCALE; v1 *= QKSCALE; }
                            uint2 u; u.x = f2tf(v0); u.y = f2tf(v1);
                            *(uint2*)&g_qkv[(size_t)part * HEADSZ +
                                (((size_t)(b * HEADS + h) * SEQ + s) * DH + d)] = u;
                        }
                    } else {
                        float2 f; f.x = v0; f.y = v1;
                        *(float2*)&out[(size_t)m * DMODEL + n] = f;
                    }
                }
            }
}

// ---------------------------------------------------------------------------
// Flash attention with LDSM fragments (no online max; Q pre-scaled, bounded).
// K smem [key][d]; V smem [d][key]; P spilled [qrow][key] (warp-private).
// 2-stage cp.async (R10 structure).
// ---------------------------------------------------------------------------
#define KST 68
#define KBUF (64 * KST)
#define PS_OFF (4 * KBUF)
#define ATT_SMEM ((PS_OFF + 128 * KST) * 4)   /* 104448 B */

__global__ __launch_bounds__(256, 2)
void attn_kernel()
{
    extern __shared__ unsigned sm[];
    const unsigned smU = (unsigned)__cvta_generic_to_shared(sm);
    unsigned* KsA = sm;                    // 2 buffers [64][68]
    unsigned* VsA = sm + 2 * KBUF;         // 2 buffers [64][68] (d-major)
    unsigned* Ps  = sm + PS_OFF;           // [128][68]
    const unsigned PsU = smU + PS_OFF * 4;

    const int tid  = threadIdx.x;
    const int warp = tid >> 5, lane = tid & 31;
    const int g = lane >> 2, l4 = lane & 3;
    const int bh = blockIdx.y;
    const int b = bh / HEADS, h = bh % HEADS;
    const int q0 = blockIdx.x * 128;
    const int qr = q0 + warp * 16;

    const int laneArow = ((lane >> 3) & 1) * 8 + (lane & 7);
    const int laneAcol = (lane >> 4) * 4;
    const int laneBrow = (lane >> 4) * 8 + (lane & 7);
    const int laneBcol = ((lane >> 3) & 1) * 4;

    const size_t base = (size_t)(b * HEADS + h) * SEQ * DH;
    const unsigned* Qg = g_qkv + base;
    const unsigned* Kg = g_qkv + HEADSZ + base;
    const unsigned* Vg = g_v + (size_t)(b * HEADS + h) * DH * SPAD;

    // Preload Q fragments (tf32, pre-scaled)
    unsigned qa[8][4];
    {
        const int r0 = qr + g, r1 = qr + g + 8;
        #pragma unroll
        for (int ks = 0; ks < 8; ks++) {
            int c0 = ks * 8 + l4;
            qa[ks][0] = (r0 < SEQ) ? Qg[r0 * DH + c0    ] : 0u;
            qa[ks][1] = (r1 < SEQ) ? Qg[r1 * DH + c0    ] : 0u;
            qa[ks][2] = (r0 < SEQ) ? Qg[r0 * DH + c0 + 4] : 0u;
            qa[ks][3] = (r1 < SEQ) ? Qg[r1 * DH + c0 + 4] : 0u;
        }
    }

    float o[8][4];
    #pragma unroll
    for (int nt = 0; nt < 8; nt++)
        #pragma unroll
        for (int r = 0; r < 4; r++) o[nt][r] = 0.f;
    float lrow[2] = {0.f, 0.f};

    auto stageKV = [&](int kt, int buf) {
        int k0 = kt * 64;
        int kv = SEQ - k0; if (kv > 64) kv = 64;
        unsigned* Kb = KsA + buf * KBUF;
        unsigned* Vb = VsA + buf * KBUF;
        #pragma unroll
        for (int it = 0; it < 4; it++) {
            int idx = tid + it * 256;
            int row = idx >> 4, q = idx & 15;
            bool pk = row < kv;
            int rk = pk ? (k0 + row) : 0;
            cp16(Kb + row * KST + q * 4, Kg + (size_t)rk * DH + q * 4, pk);
            bool pv = (q * 4) < kv;
            cp16(Vb + row * KST + q * 4, Vg + (size_t)row * SPAD + k0 + q * 4, pv);
        }
        cp_commit();
    };

    const int NTILES = (SEQ + 63) / 64;   // 10
    stageKV(0, 0);
    #pragma unroll 1
    for (int kt = 0; kt < NTILES; kt++) {
        if (kt + 1 < NTILES) { stageKV(kt + 1, (kt + 1) & 1); cp_wait<1>(); }
        else                 { cp_wait<0>(); }
        __syncthreads();

        const int k0 = kt * 64;
        int kv = SEQ - k0; if (kv > 64) kv = 64;
        const unsigned KbU = smU + (kt & 1) * KBUF * 4;
        const unsigned VbU = smU + (2 + (kt & 1)) * KBUF * 4;

        // S = Q K^T
        float s[8][4];
        #pragma unroll
        for (int nt = 0; nt < 8; nt++)
            #pragma unroll
            for (int r = 0; r < 4; r++) s[nt][r] = 0.f;

        #pragma unroll
        for (int ks = 0; ks < 8; ks++) {
            const int kk = ks * 8;
            #pragma unroll
            for (int ntp = 0; ntp < 8; ntp += 2) {
                unsigned b0, b1, b2, b3;
                LDSM4(b0, b1, b2, b3,
                      KbU + 4u * ((ntp * 8 + laneBrow) * KST + kk + laneBcol));
                mma8(s[ntp    ], qa[ks][0], qa[ks][1], qa[ks][2], qa[ks][3], b0, b1);
                mma8(s[ntp + 1], qa[ks][0], qa[ks][1], qa[ks][2], qa[ks][3], b2, b3);
            }
        }

        // exp + masked sum (no max-shift needed: scores bounded)
        #pragma unroll
        for (int r = 0; r < 2; r++) {
            float sum = 0.f;
            #pragma unroll
            for (int nt = 0; nt < 8; nt++) {
                int col = nt * 8 + 2 * l4;
                float p0 = (col     < kv) ? __expf(s[nt][2 * r    ]) : 0.f;
                float p1 = (col + 1 < kv) ? __expf(s[nt][2 * r + 1]) : 0.f;
                s[nt][2 * r] = p0; s[nt][2 * r + 1] = p1;
                sum += p0 + p1;
            }
            sum += __shfl_xor_sync(0xffffffffu, sum, 1);
            sum += __shfl_xor_sync(0xffffffffu, sum, 2);
            lrow[r] += sum;
        }

        // Spill P (tf32) to warp-private rows
        {
            const int r0 = warp * 16 + g, r1 = r0 + 8;
            #pragma unroll
            for (int nt = 0; nt < 8; nt++) {
                Ps[r0 * KST + nt * 8 + 2 * l4    ] = f2tf(s[nt][0]);
                Ps[r0 * KST + nt * 8 + 2 * l4 + 1] = f2tf(s[nt][1]);
                Ps[r1 * KST + nt * 8 + 2 * l4    ] = f2tf(s[nt][2]);
                Ps[r1 * KST + nt * 8 + 2 * l4 + 1] = f2tf(s[nt][3]);
            }
        }
        __syncwarp();

        // O += P V
        #pragma unroll
        for (int ks = 0; ks < 8; ks++) {
            const int kk = ks * 8;
            unsigned pa0, pa1, pa2, pa3;
            LDSM4(pa0, pa1, pa2, pa3,
                  PsU + 4u * ((warp * 16 + laneArow) * KST + kk + laneAcol));
            #pragma unroll
            for (int ntp = 0; ntp < 8; ntp += 2) {
                unsigned b0, b1, b2, b3;
                LDSM4(b0, b1, b2, b3,
                      VbU + 4u * ((ntp * 8 + laneBrow) * KST + kk + laneBcol));
                mma8(o[ntp    ], pa0, pa1, pa2, pa3, b0, b1);
                mma8(o[ntp + 1], pa0, pa1, pa2, pa3, b2, b3);
            }
        }
        __syncthreads();
    }

    // Normalize, write g_att (tf32)
    #pragma unroll
    for (int r = 0; r < 2; r++) {
        int row = qr + g + r * 8;
        if (row < SEQ) {
            float inv = 1.f / lrow[r];
            size_t rb = ((size_t)b * SEQ + row) * DMODEL + h * DH;
            #pragma unroll
            for (int nt = 0; nt < 8; nt++) {
                uint2 u;
                u.x = f2tf(o[nt][2 * r    ] * inv);
                u.y = f2tf(o[nt][2 * r + 1] * inv);
                *(uint2*)&g_att[rb + nt * 8 + 2 * l4] = u;
            }
        }
    }
}

// ---------------------------------------------------------------------------
extern "C" void kernel_launch(void* const* d_in, const int* in_sizes, int n_in,
                              void* d_out, int out_size)
{
    const float* x     = (const float*)d_in[0];
    const float* w_qkv = (const float*)d_in[1];
    const float* b_qkv = (const float*)d_in[2];
    const float* w_fc  = (const float*)d_in[3];
    const float* b_fc  = (const float*)d_in[4];
    float* out = (float*)d_out;

    cudaFuncSetAttribute(gemm_kernel<0>, cudaFuncAttributeMaxDynamicSharedMemorySize, GEMM_SMEM);
    cudaFuncSetAttribute(gemm_kernel<1>, cudaFuncAttributeMaxDynamicSharedMemorySize, GEMM_SMEM);
    cudaFuncSetAttribute(attn_kernel,    cudaFuncAttributeMaxDynamicSharedMemorySize, ATT_SMEM);

    // Prepass: x -> tf32; weights -> transposed tf32
    cvt_kernel<<<(HEADSZ / 4 + 255) / 256, 256>>>(x, HEADSZ / 4);
    trcvt_kernel<<<dim3(3 * DMODEL / 32, DMODEL / 32), 256>>>(w_qkv, 1, DMODEL, 3 * DMODEL);
    trcvt_kernel<<<dim3(DMODEL / 32, DMODEL / 32), 256>>>(w_fc, 2, DMODEL, DMODEL);

    const int mtiles = (MROWS + 127) / 128;   // 145
    gemm_kernel<0><<<dim3(mtiles, 18), 256, GEMM_SMEM>>>(b_qkv, nullptr, 3 * DMODEL);
    attn_kernel<<<dim3((SEQ + 127) / 128, BATCH * HEADS), 256, ATT_SMEM>>>();
    gemm_kernel<1><<<dim3(mtiles, 6), 256, GEMM_SMEM>>>(b_fc, out, DMODEL);
}